// round 15
// baseline (speedup 1.0000x reference)
#include <cuda_runtime.h>
#include <cuda_fp16.h>
#include <cstdint>
#include <math.h>

#define S 2048
#define D 2048
#define H 16
#define HD 128

// ---- scratch (allocation-free rule: __device__ globals) ----
__device__ __half g_hs_hi[S * D];
__device__ __half g_w_hi[4][D * D];
__device__ __half g_o_hi[S * D];
__device__ __half g_qh[H * S * HD];
__device__ __half g_kh[H * S * HD];
__device__ __half g_vh[H * S * HD];

// ============================================================
// helpers (arch-agnostic: mma.sync / ldmatrix / cp.async)
// ============================================================
__device__ __forceinline__ uint32_t smem_u32(const void* p) {
    uint32_t a;
    asm("{ .reg .u64 t; cvta.to.shared.u64 t, %1; cvt.u32.u64 %0, t; }"
        : "=r"(a) : "l"(p));
    return a;
}
__device__ __forceinline__ void mma16816(float* c, const uint32_t* a,
                                         const uint32_t* b) {
    asm volatile(
        "mma.sync.aligned.m16n8k16.row.col.f32.f16.f16.f32 "
        "{%0,%1,%2,%3}, {%4,%5,%6,%7}, {%8,%9}, {%0,%1,%2,%3};"
        : "+f"(c[0]), "+f"(c[1]), "+f"(c[2]), "+f"(c[3])
        : "r"(a[0]), "r"(a[1]), "r"(a[2]), "r"(a[3]), "r"(b[0]), "r"(b[1]));
}
__device__ __forceinline__ void ldsm4(uint32_t* r, uint32_t addr) {
    asm volatile("ldmatrix.sync.aligned.m8n8.x4.shared.b16 {%0,%1,%2,%3}, [%4];"
                 : "=r"(r[0]), "=r"(r[1]), "=r"(r[2]), "=r"(r[3]) : "r"(addr));
}
__device__ __forceinline__ void ldsm4t(uint32_t* r, uint32_t addr) {
    asm volatile("ldmatrix.sync.aligned.m8n8.x4.trans.shared.b16 {%0,%1,%2,%3}, [%4];"
                 : "=r"(r[0]), "=r"(r[1]), "=r"(r[2]), "=r"(r[3]) : "r"(addr));
}
#define CPASYNC16(sa, ga) \
    asm volatile("cp.async.cg.shared.global [%0], [%1], 16;" \
                 :: "r"(sa), "l"(ga) : "memory")
#define CP_COMMIT() asm volatile("cp.async.commit_group;" ::: "memory")
#define CP_WAIT(N)  asm volatile("cp.async.wait_group %0;" :: "n"(N) : "memory")

// ============================================================
// fused fp32 -> fp16 convert for 5 tensors (hs + 4 weights)
// ============================================================
__global__ __launch_bounds__(256) void conv5_kernel(
    const float* __restrict__ s0, const float* __restrict__ s1,
    const float* __restrict__ s2, const float* __restrict__ s3,
    const float* __restrict__ s4,
    __half* __restrict__ hsH, __half* __restrict__ wH, int n)
{
    int gi = blockIdx.x * 256 + threadIdx.x;
    int per = n / 4;
    int sel = gi / per;
    int i = (gi - sel * per) * 4;
    const float* src = (sel == 0) ? s0 : (sel == 1) ? s1 :
                       (sel == 2) ? s2 : (sel == 3) ? s3 : s4;
    __half* dst = (sel == 0) ? hsH : (wH + (size_t)(sel - 1) * n);
    float4 v = *(const float4*)(src + i);
    ((__half2*)(dst + i))[0] = __floats2half2_rn(v.x, v.y);
    ((__half2*)(dst + i))[1] = __floats2half2_rn(v.z, v.w);
}

// ============================================================
// QKV GEMM, CTA tile 64x128 (fine-grained: 1536 CTAs) + fused
// RoPE/IA3 epilogue. z=0 -> qh, z=1 -> kh, z=2 -> vh.
// K-stage 64, double-buffered, pitch 144B.
// ============================================================
#define PITCH 144
#define AMATSZ (64 * PITCH)        // 9216
#define BMATSZ (128 * PITCH)       // 18432
#define QSTAGE (AMATSZ + BMATSZ)   // 27648
#define QSMEM (2 * QSTAGE)         // 55296
#define FPITCH 132                 // fp32 stage pitch (floats)

__global__ __launch_bounds__(256) void gemm_qkv_kernel(
    const __half* __restrict__ Ahi, const __half* __restrict__ Wall,
    const float* __restrict__ cosT, const float* __restrict__ sinT,
    const float* __restrict__ lk, const float* __restrict__ lv,
    __half* __restrict__ qh, __half* __restrict__ kh,
    __half* __restrict__ Vh)
{
    extern __shared__ char smem[];
    const uint32_t sb = smem_u32(smem);
    const int t = threadIdx.x;
    const int lane = t & 31;
    const int w = t >> 5;
    const int mw = (w >> 2) * 32;      // 0 or 32
    const int nw = (w & 3) * 32;       // 0,32,64,96
    const int mbase = blockIdx.y * 64;
    const int nbase = blockIdx.x * 128;
    const int z = blockIdx.z;

    const __half* pA = Ahi + (size_t)mbase * 2048;
    const __half* pB = Wall + (size_t)z * (2048 * 2048) + (size_t)nbase * 2048;

    float acc[2][4][4];
#pragma unroll
    for (int i = 0; i < 2; i++)
#pragma unroll
        for (int j = 0; j < 4; j++)
#pragma unroll
            for (int k = 0; k < 4; k++) acc[i][j][k] = 0.f;

#define QLOAD_STAGE(sidx, k0) do {                                           \
        uint32_t base = sb + ((sidx) & 1) * QSTAGE;                          \
        _Pragma("unroll")                                                    \
        for (int r = 0; r < 2; r++) {                                        \
            int idx = t + 256 * r;                                           \
            int row = idx >> 3, c = idx & 7;                                 \
            CPASYNC16(base + row * PITCH + c * 16,                           \
                      pA + (size_t)row * 2048 + (k0) + c * 8);               \
        }                                                                    \
        _Pragma("unroll")                                                    \
        for (int r = 0; r < 4; r++) {                                        \
            int idx = t + 256 * r;                                           \
            int row = idx >> 3, c = idx & 7;                                 \
            CPASYNC16(base + AMATSZ + row * PITCH + c * 16,                  \
                      pB + (size_t)row * 2048 + (k0) + c * 8);               \
        }                                                                    \
        CP_COMMIT();                                                         \
    } while (0)

    QLOAD_STAGE(0, 0);
    for (int s = 0; s < 32; s++) {
        if (s < 31) { QLOAD_STAGE(s + 1, (s + 1) * 64); CP_WAIT(1); }
        else        { CP_WAIT(0); }
        __syncthreads();
        const uint32_t base = sb + (s & 1) * QSTAGE;
        const uint32_t aB = base;
        const uint32_t bB = base + AMATSZ;
#pragma unroll
        for (int ks = 0; ks < 4; ks++) {
            uint32_t a_hi[2][4], b_hi[4][2];
#pragma unroll
            for (int mt = 0; mt < 2; mt++) {
                int row = mw + mt * 16 + (lane & 15);
                int chunk = 2 * ks + (lane >> 4);
                ldsm4(a_hi[mt], aB + row * PITCH + chunk * 16);
            }
#pragma unroll
            for (int jj = 0; jj < 2; jj++) {
                int row = nw + jj * 16 + ((lane >> 4) << 3) + (lane & 7);
                int chunk = 2 * ks + ((lane >> 3) & 1);
                uint32_t rh[4];
                ldsm4(rh, bB + row * PITCH + chunk * 16);
                b_hi[2 * jj][0] = rh[0]; b_hi[2 * jj][1] = rh[1];
                b_hi[2 * jj + 1][0] = rh[2]; b_hi[2 * jj + 1][1] = rh[3];
            }
#pragma unroll
            for (int mt = 0; mt < 2; mt++)
#pragma unroll
                for (int nt = 0; nt < 4; nt++)
                    mma16816(acc[mt][nt], a_hi[mt], b_hi[nt]);
        }
        __syncthreads();
    }
#undef QLOAD_STAGE

    const int hh = nbase >> 7;

    if (z == 2) {
        // V: apply lv, emit fp16 per-head layout
#pragma unroll
        for (int mt = 0; mt < 2; mt++)
#pragma unroll
            for (int nt = 0; nt < 4; nt++) {
                const float* a = acc[mt][nt];
                int r0 = mbase + mw + mt * 16 + (lane >> 2);
                int n  = nbase + nw + nt * 8 + 2 * (lane & 3);
                size_t o0 = ((size_t)hh * 2048 + r0) * 128 + (n & 127);
                size_t o1 = ((size_t)hh * 2048 + r0 + 8) * 128 + (n & 127);
                float s0 = lv[n], s1 = lv[n + 1];
                *(__half2*)&Vh[o0] = __floats2half2_rn(a[0] * s0, a[1] * s1);
                *(__half2*)&Vh[o1] = __floats2half2_rn(a[2] * s0, a[3] * s1);
            }
        return;
    }

    // Q/K: stage fp32 acc tile (64 x 128) to smem, then rope in-CTA.
    float* f = (float*)smem;
#pragma unroll
    for (int mt = 0; mt < 2; mt++)
#pragma unroll
        for (int nt = 0; nt < 4; nt++) {
            const float* a = acc[mt][nt];
            int rl = mw + mt * 16 + (lane >> 2);
            int nl = nw + nt * 8 + 2 * (lane & 3);
            f[rl * FPITCH + nl]           = a[0];
            f[rl * FPITCH + nl + 1]       = a[1];
            f[(rl + 8) * FPITCH + nl]     = a[2];
            f[(rl + 8) * FPITCH + nl + 1] = a[3];
        }
    __syncthreads();

    const float scale = 0.08838834764831845f;   // 1/sqrt(128)
#pragma unroll 4
    for (int it = 0; it < 16; it++) {
        int idx = t + 256 * it;       // 0..4095
        int row = idx >> 6;           // 0..63
        int d   = idx & 63;           // 0..63  (partner d+64)
        float x0 = f[row * FPITCH + d];
        float x1 = f[row * FPITCH + d + 64];
        int s = mbase + row;
        float c0 = cosT[s * 128 + d],      sn0 = sinT[s * 128 + d];
        float c1 = cosT[s * 128 + d + 64], sn1 = sinT[s * 128 + d + 64];
        float r0 = x0 * c0 - x1 * sn0;    // d < 64: sign = -1
        float r1 = x1 * c1 + x0 * sn1;    // d >= 64: sign = +1
        size_t rb = ((size_t)hh * 2048 + s) * 128;
        if (z == 0) {
            r0 *= lk[hh * 128 + d] * scale;
            r1 *= lk[hh * 128 + d + 64] * scale;
            qh[rb + d]      = __float2half_rn(r0);
            qh[rb + d + 64] = __float2half_rn(r1);
        } else {
            kh[rb + d]      = __float2half_rn(r0);
            kh[rb + d + 64] = __float2half_rn(r1);
        }
    }
}

// ============================================================
// Output GEMM: out = Oh @ Wo^T, CTA tile 128x128 (R13-proven).
// ============================================================
#define MATSZ (128 * PITCH)      // 18432
#define STAGESZ (2 * MATSZ)      // 36864
#define GSMEM (2 * STAGESZ)      // 73728

__global__ __launch_bounds__(256) void gemm_out_kernel(
    const __half* __restrict__ Ahi, const __half* __restrict__ Bhi,
    float* __restrict__ C)
{
    extern __shared__ char smem[];
    const uint32_t sb = smem_u32(smem);
    const int t = threadIdx.x;
    const int lane = t & 31;
    const int w = t >> 5;
    const int mw = (w >> 1) * 32;
    const int nw = (w & 1) * 64;
    const int mbase = blockIdx.y * 128;
    const int nbase = blockIdx.x * 128;

    const __half* pA = Ahi + (size_t)mbase * 2048;
    const __half* pB = Bhi + (size_t)nbase * 2048;

    float acc[2][8][4];
#pragma unroll
    for (int i = 0; i < 2; i++)
#pragma unroll
        for (int j = 0; j < 8; j++)
#pragma unroll
            for (int k = 0; k < 4; k++) acc[i][j][k] = 0.f;

#define LOAD_STAGE(sidx, k0) do {                                            \
        uint32_t base = sb + ((sidx) & 1) * STAGESZ;                         \
        _Pragma("unroll")                                                    \
        for (int mat = 0; mat < 2; mat++) {                                  \
            const __half* g = mat ? pB : pA;                                 \
            _Pragma("unroll")                                                \
            for (int r = 0; r < 4; r++) {                                    \
                int idx = t + 256 * r;                                       \
                int row = idx >> 3, c = idx & 7;                             \
                CPASYNC16(base + mat * MATSZ + row * PITCH + c * 16,         \
                          g + (size_t)row * 2048 + (k0) + c * 8);            \
            }                                                                \
        }                                                                    \
        CP_COMMIT();                                                         \
    } while (0)

    LOAD_STAGE(0, 0);
    for (int s = 0; s < 32; s++) {
        if (s < 31) { LOAD_STAGE(s + 1, (s + 1) * 64); CP_WAIT(1); }
        else        { CP_WAIT(0); }
        __syncthreads();
        const uint32_t base = sb + (s & 1) * STAGESZ;
        const uint32_t aB = base;
        const uint32_t bB = base + MATSZ;
#pragma unroll
        for (int ks = 0; ks < 4; ks++) {
            uint32_t a_hi[2][4], b_hi[8][2];
#pragma unroll
            for (int mt = 0; mt < 2; mt++) {
                int row = mw + mt * 16 + (lane & 15);
                int chunk = 2 * ks + (lane >> 4);
                ldsm4(a_hi[mt], aB + row * PITCH + chunk * 16);
            }
#pragma unroll
            for (int j = 0; j < 4; j++) {
                int row = nw + j * 16 + ((lane >> 4) << 3) + (lane & 7);
                int chunk = 2 * ks + ((lane >> 3) & 1);
                uint32_t rh[4];
                ldsm4(rh, bB + row * PITCH + chunk * 16);
                b_hi[2 * j][0] = rh[0]; b_hi[2 * j][1] = rh[1];
                b_hi[2 * j + 1][0] = rh[2]; b_hi[2 * j + 1][1] = rh[3];
            }
#pragma unroll
            for (int mt = 0; mt < 2; mt++)
#pragma unroll
                for (int nt = 0; nt < 8; nt++)
                    mma16816(acc[mt][nt], a_hi[mt], b_hi[nt]);
        }
        __syncthreads();
    }
#undef LOAD_STAGE

#pragma unroll
    for (int mt = 0; mt < 2; mt++)
#pragma unroll
        for (int nt = 0; nt < 8; nt++) {
            const float* a = acc[mt][nt];
            int r0 = mbase + mw + mt * 16 + (lane >> 2);
            int n  = nbase + nw + nt * 8 + 2 * (lane & 3);
            *(float2*)(C + (size_t)r0 * 2048 + n)       = make_float2(a[0], a[1]);
            *(float2*)(C + (size_t)(r0 + 8) * 2048 + n) = make_float2(a[2], a[3]);
        }
}

// ============================================================
// Causal flash attention, mma.sync fp16, triangle-paired.
// Each CTA: q-tiles {15-j, j} (34 kt-iters). Grid 8x16 = 1 wave.
// ============================================================
#define FPB 272
#define QMAT (128 * FPB)
#define KVMAT (64 * FPB)

__global__ __launch_bounds__(256) void flash_mma_kernel(
    const __half* __restrict__ Qh_, const __half* __restrict__ Kh_,
    const __half* __restrict__ Vh_, __half* __restrict__ OH)
{
    extern __shared__ char smem[];
    const uint32_t sb = smem_u32(smem);
    const int t = threadIdx.x, lane = t & 31, w = t >> 5;
    const int j = blockIdx.x;
    const int h = blockIdx.y;
    const int mw = w * 16;
    const size_t hoff = (size_t)h * S * HD;
    const __half* Khp = Kh_ + hoff;
    const __half* Vhp = Vh_ + hoff;

    const uint32_t qB  = sb;
    const uint32_t kvB = sb + QMAT;

#define LOADKV(kt_, p_) do {                                                  \
        uint32_t b_ = kvB + (p_) * (2 * KVMAT);                               \
        const __half* g0 = Khp + (size_t)(kt_) * 64 * 128;                    \
        const __half* g1 = Vhp + (size_t)(kt_) * 64 * 128;                    \
        _Pragma("unroll")                                                     \
        for (int r_ = 0; r_ < 4; r_++) {                                      \
            int idx_ = t + 256 * r_;                                          \
            int row_ = idx_ >> 4, c_ = idx_ & 15;                             \
            uint32_t so_ = row_ * FPB + c_ * 16;                              \
            uint32_t go_ = row_ * 128 + c_ * 8;                               \
            CPASYNC16(b_ + so_,         g0 + go_);                            \
            CPASYNC16(b_ + KVMAT + so_, g1 + go_);                            \
        }                                                                     \
        CP_COMMIT();                                                          \
    } while (0)

    for (int sub = 0; sub < 2; sub++) {
        const int qt = sub ? j : (15 - j);
        const __half* Qhp = Qh_ + hoff + (size_t)qt * 128 * HD;

#pragma unroll
        for (int r = 0; r < 8; r++) {
            int idx = t + 256 * r;
            int row = idx >> 4, c = idx & 15;
            CPASYNC16(qB + row * FPB + c * 16, Qhp + row * 128 + c * 8);
        }
        CP_COMMIT();

        float acc[16][4];
#pragma unroll
        for (int i = 0; i < 16; i++)
#pragma unroll
            for (int jj = 0; jj < 4; jj++) acc[i][jj] = 0.f;
        float m0 = -1e30f, m1 = -1e30f, l0 = 0.f, l1 = 0.f;

        const int ktmax = 2 * qt + 1;
        LOADKV(0, 0);

        for (int kt = 0; kt <= ktmax; kt++) {
            if (kt < ktmax) { LOADKV(kt + 1, (kt + 1) & 1); CP_WAIT(1); }
            else            { CP_WAIT(0); }
            __syncthreads();
            const uint32_t base = kvB + (kt & 1) * (2 * KVMAT);

            float s[8][4];
#pragma unroll
            for (int i = 0; i < 8; i++)
#pragma unroll
                for (int jj = 0; jj < 4; jj++) s[i][jj] = 0.f;
#pragma unroll
            for (int kc = 0; kc < 8; kc++) {
                uint32_t aH[4];
                ldsm4(aH, qB + (mw + (lane & 15)) * FPB + (2 * kc + (lane >> 4)) * 16);
                uint32_t bH[8][2];
#pragma unroll
                for (int jj = 0; jj < 4; jj++) {
                    int row = jj * 16 + ((lane >> 4) << 3) + (lane & 7);
                    uint32_t rh[4];
                    ldsm4(rh, base + row * FPB + (2 * kc + ((lane >> 3) & 1)) * 16);
                    bH[2 * jj][0] = rh[0]; bH[2 * jj][1] = rh[1];
                    bH[2 * jj + 1][0] = rh[2]; bH[2 * jj + 1][1] = rh[3];
                }
#pragma unroll
                for (int nb = 0; nb < 8; nb++)
                    mma16816(s[nb], aH, bH[nb]);
            }

            const int qrow = qt * 128 + mw + (lane >> 2);
            if (kt * 64 + 63 > qt * 128 + mw) {
#pragma unroll
                for (int nb = 0; nb < 8; nb++) {
                    int col = kt * 64 + 8 * nb + 2 * (lane & 3);
                    if (col     > qrow)     s[nb][0] = -1e30f;
                    if (col + 1 > qrow)     s[nb][1] = -1e30f;
                    if (col     > qrow + 8) s[nb][2] = -1e30f;
                    if (col + 1 > qrow + 8) s[nb][3] = -1e30f;
                }
            }

            float mx0 = -1e30f, mx1 = -1e30f;
#pragma unroll
            for (int nb = 0; nb < 8; nb++) {
                mx0 = fmaxf(mx0, fmaxf(s[nb][0], s[nb][1]));
                mx1 = fmaxf(mx1, fmaxf(s[nb][2], s[nb][3]));
            }
            mx0 = fmaxf(mx0, __shfl_xor_sync(0xffffffffu, mx0, 1));
            mx0 = fmaxf(mx0, __shfl_xor_sync(0xffffffffu, mx0, 2));
            mx1 = fmaxf(mx1, __shfl_xor_sync(0xffffffffu, mx1, 1));
            mx1 = fmaxf(mx1, __shfl_xor_sync(0xffffffffu, mx1, 2));
            float mn0 = fmaxf(m0, mx0), mn1 = fmaxf(m1, mx1);
            float al0 = __expf(m0 - mn0), al1 = __expf(m1 - mn1);
            m0 = mn0; m1 = mn1;

            float sum0 = 0.f, sum1 = 0.f;
            uint32_t ph0[8], ph1[8];
#pragma unroll
            for (int nb = 0; nb < 8; nb++) {
                float p0 = __expf(s[nb][0] - mn0), p1 = __expf(s[nb][1] - mn0);
                float p2 = __expf(s[nb][2] - mn1), p3 = __expf(s[nb][3] - mn1);
                sum0 += p0 + p1; sum1 += p2 + p3;
                __half2 h01 = __floats2half2_rn(p0, p1);
                __half2 h23 = __floats2half2_rn(p2, p3);
                ph0[nb] = *(uint32_t*)&h01;
                ph1[nb] = *(uint32_t*)&h23;
            }
            sum0 += __shfl_xor_sync(0xffffffffu, sum0, 1);
            sum0 += __shfl_xor_sync(0xffffffffu, sum0, 2);
            sum1 += __shfl_xor_sync(0xffffffffu, sum1, 1);
            sum1 += __shfl_xor_sync(0xffffffffu, sum1, 2);
            l0 = l0 * al0 + sum0;
            l1 = l1 * al1 + sum1;
#pragma unroll
            for (int nb = 0; nb < 16; nb++) {
                acc[nb][0] *= al0; acc[nb][1] *= al0;
                acc[nb][2] *= al1; acc[nb][3] *= al1;
            }

#pragma unroll
            for (int kc = 0; kc < 4; kc++) {
                uint32_t paH[4] = {ph0[2 * kc], ph1[2 * kc],
                                   ph0[2 * kc + 1], ph1[2 * kc + 1]};
#pragma unroll
                for (int nb2 = 0; nb2 < 8; nb2++) {
                    uint32_t vaddr = base + KVMAT +
                                     (kc * 16 + (lane & 15)) * FPB +
                                     (2 * nb2 + (lane >> 4)) * 16;
                    uint32_t vh[4];
                    ldsm4t(vh, vaddr);
                    uint32_t bh0[2] = {vh[0], vh[1]}, bh1[2] = {vh[2], vh[3]};
                    mma16816(acc[2 * nb2], paH, bh0);
                    mma16816(acc[2 * nb2 + 1], paH, bh1);
                }
            }
            __syncthreads();
        }

        float inv0 = 1.f / l0, inv1 = 1.f / l1;
        int r = qt * 128 + mw + (lane >> 2);
#pragma unroll
        for (int nb = 0; nb < 16; nb++) {
            int col = h * 128 + 8 * nb + 2 * (lane & 3);
            *(__half2*)&OH[(size_t)r * D + col] =
                __floats2half2_rn(acc[nb][0] * inv0, acc[nb][1] * inv0);
            *(__half2*)&OH[(size_t)(r + 8) * D + col] =
                __floats2half2_rn(acc[nb][2] * inv1, acc[nb][3] * inv1);
        }
    }
}

// ============================================================
extern "C" void kernel_launch(void* const* d_in, const int* in_sizes, int n_in,
                              void* d_out, int out_size)
{
    const float* hs   = (const float*)d_in[0];
    const float* cosT = (const float*)d_in[2];
    const float* sinT = (const float*)d_in[3];
    const float* Wq   = (const float*)d_in[4];
    const float* Wk   = (const float*)d_in[5];
    const float* Wv   = (const float*)d_in[6];
    const float* Wo   = (const float*)d_in[7];
    const float* lk   = (const float*)d_in[8];
    const float* lv   = (const float*)d_in[9];
    float* out = (float*)d_out;
    (void)in_sizes; (void)n_in; (void)out_size;

    __half *hsH, *wH, *oH, *qh, *kh, *vh;
    cudaGetSymbolAddress((void**)&hsH, g_hs_hi);
    cudaGetSymbolAddress((void**)&wH, g_w_hi);
    cudaGetSymbolAddress((void**)&oH, g_o_hi);
    cudaGetSymbolAddress((void**)&qh, g_qh);
    cudaGetSymbolAddress((void**)&kh, g_kh);
    cudaGetSymbolAddress((void**)&vh, g_vh);

    const int n = S * D;
    conv5_kernel<<<5 * (n / 4) / 256, 256>>>(hs, Wq, Wk, Wv, Wo, hsH, wH, n);

    cudaFuncSetAttribute(gemm_qkv_kernel,
                         cudaFuncAttributeMaxDynamicSharedMemorySize, QSMEM);
    cudaFuncSetAttribute(gemm_out_kernel,
                         cudaFuncAttributeMaxDynamicSharedMemorySize, GSMEM);

    gemm_qkv_kernel<<<dim3(D / 128, S / 64, 3), 256, QSMEM>>>(
        hsH, wH, cosT, sinT, lk, lv, qh, kh, vh);

    int fsmem = QMAT + 2 * 2 * KVMAT;   // 104448
    cudaFuncSetAttribute(flash_mma_kernel,
                         cudaFuncAttributeMaxDynamicSharedMemorySize, fsmem);
    flash_mma_kernel<<<dim3(8, 16), 256, fsmem>>>(qh, kh, vh, oH);

    gemm_out_kernel<<<dim3(D / 128, S / 128), 256, GSMEM>>>(
        oH, wH + 3 * (size_t)n, out);
}

// round 16
// speedup vs baseline: 1.0420x; 1.0420x over previous
#include <cuda_runtime.h>
#include <cuda_fp16.h>
#include <cstdint>
#include <math.h>

#define S 2048
#define D 2048
#define H 16
#define HD 128

// ---- scratch (allocation-free rule: __device__ globals) ----
__device__ __half g_hs_hi[S * D];
__device__ __half g_w_hi[4][D * D];
__device__ __half g_o_hi[S * D];
__device__ __half g_qh[H * S * HD];
__device__ __half g_kh[H * S * HD];
__device__ __half g_vh[H * S * HD];

// ============================================================
// helpers (arch-agnostic: mma.sync / ldmatrix / cp.async)
// ============================================================
__device__ __forceinline__ uint32_t smem_u32(const void* p) {
    uint32_t a;
    asm("{ .reg .u64 t; cvta.to.shared.u64 t, %1; cvt.u32.u64 %0, t; }"
        : "=r"(a) : "l"(p));
    return a;
}
__device__ __forceinline__ void mma16816(float* c, const uint32_t* a,
                                         const uint32_t* b) {
    asm volatile(
        "mma.sync.aligned.m16n8k16.row.col.f32.f16.f16.f32 "
        "{%0,%1,%2,%3}, {%4,%5,%6,%7}, {%8,%9}, {%0,%1,%2,%3};"
        : "+f"(c[0]), "+f"(c[1]), "+f"(c[2]), "+f"(c[3])
        : "r"(a[0]), "r"(a[1]), "r"(a[2]), "r"(a[3]), "r"(b[0]), "r"(b[1]));
}
__device__ __forceinline__ void ldsm4(uint32_t* r, uint32_t addr) {
    asm volatile("ldmatrix.sync.aligned.m8n8.x4.shared.b16 {%0,%1,%2,%3}, [%4];"
                 : "=r"(r[0]), "=r"(r[1]), "=r"(r[2]), "=r"(r[3]) : "r"(addr));
}
__device__ __forceinline__ void ldsm4t(uint32_t* r, uint32_t addr) {
    asm volatile("ldmatrix.sync.aligned.m8n8.x4.trans.shared.b16 {%0,%1,%2,%3}, [%4];"
                 : "=r"(r[0]), "=r"(r[1]), "=r"(r[2]), "=r"(r[3]) : "r"(addr));
}
#define CPASYNC16(sa, ga) \
    asm volatile("cp.async.cg.shared.global [%0], [%1], 16;" \
                 :: "r"(sa), "l"(ga) : "memory")
#define CP_COMMIT() asm volatile("cp.async.commit_group;" ::: "memory")
#define CP_WAIT(N)  asm volatile("cp.async.wait_group %0;" :: "n"(N) : "memory")

// ============================================================
// fused fp32 -> fp16 convert for 5 tensors (hs + 4 weights)
// ============================================================
__global__ __launch_bounds__(256) void conv5_kernel(
    const float* __restrict__ s0, const float* __restrict__ s1,
    const float* __restrict__ s2, const float* __restrict__ s3,
    const float* __restrict__ s4,
    __half* __restrict__ hsH, __half* __restrict__ wH, int n)
{
    int gi = blockIdx.x * 256 + threadIdx.x;
    int per = n / 4;
    int sel = gi / per;
    int i = (gi - sel * per) * 4;
    const float* src = (sel == 0) ? s0 : (sel == 1) ? s1 :
                       (sel == 2) ? s2 : (sel == 3) ? s3 : s4;
    __half* dst = (sel == 0) ? hsH : (wH + (size_t)(sel - 1) * n);
    float4 v = *(const float4*)(src + i);
    ((__half2*)(dst + i))[0] = __floats2half2_rn(v.x, v.y);
    ((__half2*)(dst + i))[1] = __floats2half2_rn(v.z, v.w);
}

// ============================================================
// Fused QKV GEMM + RoPE/IA3 epilogue (R13-proven 128x128 tile).
// z=0 -> qh = rope(hs@Wq^T) * lk * scale (fp16)
// z=1 -> kh = rope(hs@Wk^T) (fp16)
// z=2 -> vh = (hs@Wv^T) * lv (fp16)
// CTA tile 128x128, K-stage 64, double-buffered.
// ============================================================
#define PITCH 144
#define MATSZ (128 * PITCH)      // 18432
#define STAGESZ (2 * MATSZ)      // 36864
#define GSMEM (2 * STAGESZ)      // 73728
#define FPITCH 132               // fp32 stage pitch (floats)

template <int BODY>
__device__ __forceinline__ void gemm_body(
    const __half* pA, const __half* pB, uint32_t sb,
    int t, int lane, int mw, int nw, float acc[2][8][4])
{
#define LOAD_STAGE(sidx, k0) do {                                            \
        uint32_t base = sb + ((sidx) & 1) * STAGESZ;                         \
        _Pragma("unroll")                                                    \
        for (int mat = 0; mat < 2; mat++) {                                  \
            const __half* g = mat ? pB : pA;                                 \
            _Pragma("unroll")                                                \
            for (int r = 0; r < 4; r++) {                                    \
                int idx = t + 256 * r;                                       \
                int row = idx >> 3, c = idx & 7;                             \
                CPASYNC16(base + mat * MATSZ + row * PITCH + c * 16,         \
                          g + (size_t)row * 2048 + (k0) + c * 8);            \
            }                                                                \
        }                                                                    \
        CP_COMMIT();                                                         \
    } while (0)

    LOAD_STAGE(0, 0);
    for (int s = 0; s < 32; s++) {
        if (s < 31) { LOAD_STAGE(s + 1, (s + 1) * 64); CP_WAIT(1); }
        else        { CP_WAIT(0); }
        __syncthreads();
        const uint32_t base = sb + (s & 1) * STAGESZ;
        const uint32_t aB = base;
        const uint32_t bB = base + MATSZ;
#pragma unroll
        for (int ks = 0; ks < 4; ks++) {
            uint32_t a_hi[2][4], b_hi[8][2];
#pragma unroll
            for (int mt = 0; mt < 2; mt++) {
                int row = mw + mt * 16 + (lane & 15);
                int chunk = 2 * ks + (lane >> 4);
                ldsm4(a_hi[mt], aB + row * PITCH + chunk * 16);
            }
#pragma unroll
            for (int j = 0; j < 4; j++) {
                int row = nw + j * 16 + ((lane >> 4) << 3) + (lane & 7);
                int chunk = 2 * ks + ((lane >> 3) & 1);
                uint32_t rh[4];
                ldsm4(rh, bB + row * PITCH + chunk * 16);
                b_hi[2 * j][0] = rh[0]; b_hi[2 * j][1] = rh[1];
                b_hi[2 * j + 1][0] = rh[2]; b_hi[2 * j + 1][1] = rh[3];
            }
#pragma unroll
            for (int mt = 0; mt < 2; mt++)
#pragma unroll
                for (int nt = 0; nt < 8; nt++)
                    mma16816(acc[mt][nt], a_hi[mt], b_hi[nt]);
        }
        __syncthreads();
    }
#undef LOAD_STAGE
}

__global__ __launch_bounds__(256) void gemm_qkv_kernel(
    const __half* __restrict__ Ahi, const __half* __restrict__ Wall,
    const float* __restrict__ cosT, const float* __restrict__ sinT,
    const float* __restrict__ lk, const float* __restrict__ lv,
    __half* __restrict__ qh, __half* __restrict__ kh,
    __half* __restrict__ Vh)
{
    extern __shared__ char smem[];
    const uint32_t sb = smem_u32(smem);
    const int t = threadIdx.x;
    const int lane = t & 31;
    const int w = t >> 5;
    const int mw = (w >> 1) * 32;
    const int nw = (w & 1) * 64;
    const int mbase = blockIdx.y * 128;
    const int nbase = blockIdx.x * 128;
    const int z = blockIdx.z;

    const __half* pA = Ahi + (size_t)mbase * 2048;
    const __half* pB = Wall + (size_t)z * (2048 * 2048) + (size_t)nbase * 2048;

    float acc[2][8][4];
#pragma unroll
    for (int i = 0; i < 2; i++)
#pragma unroll
        for (int j = 0; j < 8; j++)
#pragma unroll
            for (int k = 0; k < 4; k++) acc[i][j][k] = 0.f;

    gemm_body<0>(pA, pB, sb, t, lane, mw, nw, acc);

    const int hh = nbase >> 7;

    if (z == 2) {
        // V: apply lv, emit fp16 per-head layout
#pragma unroll
        for (int mt = 0; mt < 2; mt++)
#pragma unroll
            for (int nt = 0; nt < 8; nt++) {
                const float* a = acc[mt][nt];
                int r0 = mbase + mw + mt * 16 + (lane >> 2);
                int n  = nbase + nw + nt * 8 + 2 * (lane & 3);
                size_t o0 = ((size_t)hh * 2048 + r0) * 128 + (n & 127);
                size_t o1 = ((size_t)hh * 2048 + r0 + 8) * 128 + (n & 127);
                float s0 = lv[n], s1 = lv[n + 1];
                *(__half2*)&Vh[o0] = __floats2half2_rn(a[0] * s0, a[1] * s1);
                *(__half2*)&Vh[o1] = __floats2half2_rn(a[2] * s0, a[3] * s1);
            }
        return;
    }

    // Q/K: stage fp32 acc tile to smem, then rope in-CTA.
    float* f = (float*)smem;
#pragma unroll
    for (int mt = 0; mt < 2; mt++)
#pragma unroll
        for (int nt = 0; nt < 8; nt++) {
            const float* a = acc[mt][nt];
            int rl = mw + mt * 16 + (lane >> 2);
            int nl = nw + nt * 8 + 2 * (lane & 3);
            f[rl * FPITCH + nl]           = a[0];
            f[rl * FPITCH + nl + 1]       = a[1];
            f[(rl + 8) * FPITCH + nl]     = a[2];
            f[(rl + 8) * FPITCH + nl + 1] = a[3];
        }
    __syncthreads();

    const float scale = 0.08838834764831845f;   // 1/sqrt(128)
#pragma unroll 4
    for (int it = 0; it < 32; it++) {
        int idx = t + 256 * it;       // 0..8191
        int row = idx >> 6;           // 0..127
        int d   = idx & 63;           // 0..63  (partner d+64)
        float x0 = f[row * FPITCH + d];
        float x1 = f[row * FPITCH + d + 64];
        int s = mbase + row;
        float c0 = cosT[s * 128 + d],      sn0 = sinT[s * 128 + d];
        float c1 = cosT[s * 128 + d + 64], sn1 = sinT[s * 128 + d + 64];
        float r0 = x0 * c0 - x1 * sn0;    // d < 64: sign = -1
        float r1 = x1 * c1 + x0 * sn1;    // d >= 64: sign = +1
        size_t rb = ((size_t)hh * 2048 + s) * 128;
        if (z == 0) {
            r0 *= lk[hh * 128 + d] * scale;
            r1 *= lk[hh * 128 + d + 64] * scale;
            qh[rb + d]      = __float2half_rn(r0);
            qh[rb + d + 64] = __float2half_rn(r1);
        } else {
            kh[rb + d]      = __float2half_rn(r0);
            kh[rb + d + 64] = __float2half_rn(r1);
        }
    }
}

__global__ __launch_bounds__(256) void gemm_out_kernel(
    const __half* __restrict__ Ahi, const __half* __restrict__ Bhi,
    float* __restrict__ C)
{
    extern __shared__ char smem[];
    const uint32_t sb = smem_u32(smem);
    const int t = threadIdx.x;
    const int lane = t & 31;
    const int w = t >> 5;
    const int mw = (w >> 1) * 32;
    const int nw = (w & 1) * 64;
    const int mbase = blockIdx.y * 128;
    const int nbase = blockIdx.x * 128;

    const __half* pA = Ahi + (size_t)mbase * 2048;
    const __half* pB = Bhi + (size_t)nbase * 2048;

    float acc[2][8][4];
#pragma unroll
    for (int i = 0; i < 2; i++)
#pragma unroll
        for (int j = 0; j < 8; j++)
#pragma unroll
            for (int k = 0; k < 4; k++) acc[i][j][k] = 0.f;

    gemm_body<1>(pA, pB, sb, t, lane, mw, nw, acc);

#pragma unroll
    for (int mt = 0; mt < 2; mt++)
#pragma unroll
        for (int nt = 0; nt < 8; nt++) {
            const float* a = acc[mt][nt];
            int r0 = mbase + mw + mt * 16 + (lane >> 2);
            int n  = nbase + nw + nt * 8 + 2 * (lane & 3);
            *(float2*)(C + (size_t)r0 * 2048 + n)       = make_float2(a[0], a[1]);
            *(float2*)(C + (size_t)(r0 + 8) * 2048 + n) = make_float2(a[2], a[3]);
        }
}

// ============================================================
// Causal flash attention, mma.sync fp16, triangle-paired.
// Each CTA: q-tiles {15-j, j}. Fully-masked diagonal warps skip
// their iteration body (exact: their contribution is zero).
// Grid 8x16 = 1 wave.
// ============================================================
#define FPB 272
#define QMAT (128 * FPB)
#define KVMAT (64 * FPB)

__global__ __launch_bounds__(256) void flash_mma_kernel(
    const __half* __restrict__ Qh_, const __half* __restrict__ Kh_,
    const __half* __restrict__ Vh_, __half* __restrict__ OH)
{
    extern __shared__ char smem[];
    const uint32_t sb = smem_u32(smem);
    const int t = threadIdx.x, lane = t & 31, w = t >> 5;
    const int j = blockIdx.x;
    const int h = blockIdx.y;
    const int mw = w * 16;
    const size_t hoff = (size_t)h * S * HD;
    const __half* Khp = Kh_ + hoff;
    const __half* Vhp = Vh_ + hoff;

    const uint32_t qB  = sb;
    const uint32_t kvB = sb + QMAT;

#define LOADKV(kt_, p_) do {                                                  \
        uint32_t b_ = kvB + (p_) * (2 * KVMAT);                               \
        const __half* g0 = Khp + (size_t)(kt_) * 64 * 128;                    \
        const __half* g1 = Vhp + (size_t)(kt_) * 64 * 128;                    \
        _Pragma("unroll")                                                     \
        for (int r_ = 0; r_ < 4; r_++) {                                      \
            int idx_ = t + 256 * r_;                                          \
            int row_ = idx_ >> 4, c_ = idx_ & 15;                             \
            uint32_t so_ = row_ * FPB + c_ * 16;                              \
            uint32_t go_ = row_ * 128 + c_ * 8;                               \
            CPASYNC16(b_ + so_,         g0 + go_);                            \
            CPASYNC16(b_ + KVMAT + so_, g1 + go_);                            \
        }                                                                     \
        CP_COMMIT();                                                          \
    } while (0)

    for (int sub = 0; sub < 2; sub++) {
        const int qt = sub ? j : (15 - j);
        const __half* Qhp = Qh_ + hoff + (size_t)qt * 128 * HD;

#pragma unroll
        for (int r = 0; r < 8; r++) {
            int idx = t + 256 * r;
            int row = idx >> 4, c = idx & 15;
            CPASYNC16(qB + row * FPB + c * 16, Qhp + row * 128 + c * 8);
        }
        CP_COMMIT();

        float acc[16][4];
#pragma unroll
        for (int i = 0; i < 16; i++)
#pragma unroll
            for (int jj = 0; jj < 4; jj++) acc[i][jj] = 0.f;
        float m0 = -1e30f, m1 = -1e30f, l0 = 0.f, l1 = 0.f;

        const int ktmax = 2 * qt + 1;
        const int qrow_max = qt * 128 + mw + 15;   // this warp's last row
        LOADKV(0, 0);

        for (int kt = 0; kt <= ktmax; kt++) {
            if (kt < ktmax) { LOADKV(kt + 1, (kt + 1) & 1); CP_WAIT(1); }
            else            { CP_WAIT(0); }
            __syncthreads();
            const uint32_t base = kvB + (kt & 1) * (2 * KVMAT);

            // Fully-masked diagonal block for this warp: contribution
            // is exactly zero -> skip the body, keep the barriers.
            if (kt * 64 <= qrow_max) {

            float s[8][4];
#pragma unroll
            for (int i = 0; i < 8; i++)
#pragma unroll
                for (int jj = 0; jj < 4; jj++) s[i][jj] = 0.f;
#pragma unroll
            for (int kc = 0; kc < 8; kc++) {
                uint32_t aH[4];
                ldsm4(aH, qB + (mw + (lane & 15)) * FPB + (2 * kc + (lane >> 4)) * 16);
                uint32_t bH[8][2];
#pragma unroll
                for (int jj = 0; jj < 4; jj++) {
                    int row = jj * 16 + ((lane >> 4) << 3) + (lane & 7);
                    uint32_t rh[4];
                    ldsm4(rh, base + row * FPB + (2 * kc + ((lane >> 3) & 1)) * 16);
                    bH[2 * jj][0] = rh[0]; bH[2 * jj][1] = rh[1];
                    bH[2 * jj + 1][0] = rh[2]; bH[2 * jj + 1][1] = rh[3];
                }
#pragma unroll
                for (int nb = 0; nb < 8; nb++)
                    mma16816(s[nb], aH, bH[nb]);
            }

            const int qrow = qt * 128 + mw + (lane >> 2);
            if (kt * 64 + 63 > qt * 128 + mw) {
#pragma unroll
                for (int nb = 0; nb < 8; nb++) {
                    int col = kt * 64 + 8 * nb + 2 * (lane & 3);
                    if (col     > qrow)     s[nb][0] = -1e30f;
                    if (col + 1 > qrow)     s[nb][1] = -1e30f;
                    if (col     > qrow + 8) s[nb][2] = -1e30f;
                    if (col + 1 > qrow + 8) s[nb][3] = -1e30f;
                }
            }

            float mx0 = -1e30f, mx1 = -1e30f;
#pragma unroll
            for (int nb = 0; nb < 8; nb++) {
                mx0 = fmaxf(mx0, fmaxf(s[nb][0], s[nb][1]));
                mx1 = fmaxf(mx1, fmaxf(s[nb][2], s[nb][3]));
            }
            mx0 = fmaxf(mx0, __shfl_xor_sync(0xffffffffu, mx0, 1));
            mx0 = fmaxf(mx0, __shfl_xor_sync(0xffffffffu, mx0, 2));
            mx1 = fmaxf(mx1, __shfl_xor_sync(0xffffffffu, mx1, 1));
            mx1 = fmaxf(mx1, __shfl_xor_sync(0xffffffffu, mx1, 2));
            float mn0 = fmaxf(m0, mx0), mn1 = fmaxf(m1, mx1);
            float al0 = __expf(m0 - mn0), al1 = __expf(m1 - mn1);
            m0 = mn0; m1 = mn1;

            float sum0 = 0.f, sum1 = 0.f;
            uint32_t ph0[8], ph1[8];
#pragma unroll
            for (int nb = 0; nb < 8; nb++) {
                float p0 = __expf(s[nb][0] - mn0), p1 = __expf(s[nb][1] - mn0);
                float p2 = __expf(s[nb][2] - mn1), p3 = __expf(s[nb][3] - mn1);
                sum0 += p0 + p1; sum1 += p2 + p3;
                __half2 h01 = __floats2half2_rn(p0, p1);
                __half2 h23 = __floats2half2_rn(p2, p3);
                ph0[nb] = *(uint32_t*)&h01;
                ph1[nb] = *(uint32_t*)&h23;
            }
            sum0 += __shfl_xor_sync(0xffffffffu, sum0, 1);
            sum0 += __shfl_xor_sync(0xffffffffu, sum0, 2);
            sum1 += __shfl_xor_sync(0xffffffffu, sum1, 1);
            sum1 += __shfl_xor_sync(0xffffffffu, sum1, 2);
            l0 = l0 * al0 + sum0;
            l1 = l1 * al1 + sum1;
#pragma unroll
            for (int nb = 0; nb < 16; nb++) {
                acc[nb][0] *= al0; acc[nb][1] *= al0;
                acc[nb][2] *= al1; acc[nb][3] *= al1;
            }

#pragma unroll
            for (int kc = 0; kc < 4; kc++) {
                uint32_t paH[4] = {ph0[2 * kc], ph1[2 * kc],
                                   ph0[2 * kc + 1], ph1[2 * kc + 1]};
#pragma unroll
                for (int nb2 = 0; nb2 < 8; nb2++) {
                    uint32_t vaddr = base + KVMAT +
                                     (kc * 16 + (lane & 15)) * FPB +
                                     (2 * nb2 + (lane >> 4)) * 16;
                    uint32_t vh[4];
                    ldsm4t(vh, vaddr);
                    uint32_t bh0[2] = {vh[0], vh[1]}, bh1[2] = {vh[2], vh[3]};
                    mma16816(acc[2 * nb2], paH, bh0);
                    mma16816(acc[2 * nb2 + 1], paH, bh1);
                }
            }

            }   // end active-warp body
            __syncthreads();
        }

        float inv0 = 1.f / l0, inv1 = 1.f / l1;
        int r = qt * 128 + mw + (lane >> 2);
#pragma unroll
        for (int nb = 0; nb < 16; nb++) {
            int col = h * 128 + 8 * nb + 2 * (lane & 3);
            *(__half2*)&OH[(size_t)r * D + col] =
                __floats2half2_rn(acc[nb][0] * inv0, acc[nb][1] * inv0);
            *(__half2*)&OH[(size_t)(r + 8) * D + col] =
                __floats2half2_rn(acc[nb][2] * inv1, acc[nb][3] * inv1);
        }
    }
}

// ============================================================
extern "C" void kernel_launch(void* const* d_in, const int* in_sizes, int n_in,
                              void* d_out, int out_size)
{
    const float* hs   = (const float*)d_in[0];
    const float* cosT = (const float*)d_in[2];
    const float* sinT = (const float*)d_in[3];
    const float* Wq   = (const float*)d_in[4];
    const float* Wk   = (const float*)d_in[5];
    const float* Wv   = (const float*)d_in[6];
    const float* Wo   = (const float*)d_in[7];
    const float* lk   = (const float*)d_in[8];
    const float* lv   = (const float*)d_in[9];
    float* out = (float*)d_out;
    (void)in_sizes; (void)n_in; (void)out_size;

    __half *hsH, *wH, *oH, *qh, *kh, *vh;
    cudaGetSymbolAddress((void**)&hsH, g_hs_hi);
    cudaGetSymbolAddress((void**)&wH, g_w_hi);
    cudaGetSymbolAddress((void**)&oH, g_o_hi);
    cudaGetSymbolAddress((void**)&qh, g_qh);
    cudaGetSymbolAddress((void**)&kh, g_kh);
    cudaGetSymbolAddress((void**)&vh, g_vh);

    const int n = S * D;
    conv5_kernel<<<5 * (n / 4) / 256, 256>>>(hs, Wq, Wk, Wv, Wo, hsH, wH, n);

    cudaFuncSetAttribute(gemm_qkv_kernel,
                         cudaFuncAttributeMaxDynamicSharedMemorySize, GSMEM);
    cudaFuncSetAttribute(gemm_out_kernel,
                         cudaFuncAttributeMaxDynamicSharedMemorySize, GSMEM);

    gemm_qkv_kernel<<<dim3(D / 128, S / 128, 3), 256, GSMEM>>>(
        hsH, wH, cosT, sinT, lk, lv, qh, kh, vh);

    int fsmem = QMAT + 2 * 2 * KVMAT;   // 104448
    cudaFuncSetAttribute(flash_mma_kernel,
                         cudaFuncAttributeMaxDynamicSharedMemorySize, fsmem);
    flash_mma_kernel<<<dim3(8, 16), 256, fsmem>>>(qh, kh, vh, oH);

    gemm_out_kernel<<<dim3(D / 128, S / 128), 256, GSMEM>>>(
        oH, wH + 3 * (size_t)n, out);
}